// round 5
// baseline (speedup 1.0000x reference)
#include <cuda_runtime.h>
#include <cuda_bf16.h>
#include <math.h>

#define BN 4
#define HH 192
#define WW 192
#define PP (HH*WW)           // 36864
#define CF 64
#define ONC 64
#define INC 7
#define PTILES (PP/128)      // 288

typedef unsigned long long u64;

__device__ __forceinline__ void fma2(u64& a, u64 x, u64 w) {
    asm("fma.rn.f32x2 %0, %1, %2, %0;" : "+l"(a) : "l"(x), "l"(w));
}
__device__ __forceinline__ u64 pack2(float s) {
    u64 r; unsigned si = __float_as_uint(s);
    asm("mov.b64 %0, {%1, %2};" : "=l"(r) : "r"(si), "r"(si));
    return r;
}
__device__ __forceinline__ float2 unpack2(u64 v) {
    float2 f; unsigned lo, hi;
    asm("mov.b64 {%0, %1}, %2;" : "=r"(lo), "=r"(hi) : "l"(v));
    f.x = __uint_as_float(lo); f.y = __uint_as_float(hi);
    return f;
}

// ---------------- scratch (device globals; no runtime allocation) ----------------
__device__ float g_dw[BN * CF * PP];            // depthwise output
__device__ float g_om[BN * 525 * PP];           // offset/mask (max k=5)
__device__ float g_stack[BN * 3 * ONC * PP];    // stacked branch outputs
__device__ float g_attp[BN * ONC * PTILES];     // attn partial sums
__device__ float g_att[BN * ONC];
__device__ float g_atts[BN * 3 * ONC];
__device__ float g_Wb[BN * ONC * 3 * ONC];      // per-batch scaled conv_w

// ---------------- depthwise conv (k = 1,3,5, SAME padding), 4 px / thread ----------------
template <int KK>
__global__ void dw_conv_kernel(const float* __restrict__ x,
                               const float* __restrict__ w,
                               const float* __restrict__ bias,
                               float* __restrict__ y)
{
    const int P4 = PP / 4;
    int idx = blockIdx.x * blockDim.x + threadIdx.x;
    if (idx >= BN * CF * P4) return;
    int p4 = idx % P4;
    int c  = (idx / P4) % CF;
    int b  = idx / (CF * P4);
    int p  = p4 * 4;
    int h  = p / WW;
    int x0 = p - h * WW;
    const int pad = KK / 2;
    const float* xp = x + ((long)(b * CF + c)) * PP;
    const float* wp = w + c * KK * KK;

    float acc[4];
    float bb = bias[c];
#pragma unroll
    for (int i = 0; i < 4; i++) acc[i] = bb;

    bool inter = (h >= pad) && (h < HH - pad) && (x0 >= pad) && (x0 + 3 + pad < WW);

#pragma unroll
    for (int ky = 0; ky < KK; ky++) {
        int yy = h + ky - pad;
        const float* r = xp + yy * WW + x0 - pad;
        float v[KK + 3];
        if (inter) {
#pragma unroll
            for (int m = 0; m < KK + 3; m++) v[m] = r[m];
        } else {
            bool vy = (yy >= 0) && (yy < HH);
#pragma unroll
            for (int m = 0; m < KK + 3; m++) {
                int xx = x0 - pad + m;
                v[m] = (vy && xx >= 0 && xx < WW) ? xp[yy * WW + xx] : 0.f;
            }
        }
#pragma unroll
        for (int kx = 0; kx < KK; kx++) {
            float wv = wp[ky * KK + kx];
#pragma unroll
            for (int i = 0; i < 4; i++) acc[i] += v[i + kx] * wv;
        }
    }
    float4 o4 = make_float4(acc[0], acc[1], acc[2], acc[3]);
    *reinterpret_cast<float4*>(y + (long)idx * 4) = o4;
}

// ---------------- pointwise GEMM: Y[b,oc,p] = sum_c W[oc,c]*X[b,c,p] + bias ----------------
// tile: 128 px x 64 oc, 256 threads, 8px x 4oc micro-tile, packed f32x2 FMA
__global__ void pw_gemm_kernel(const float* __restrict__ X,
                               const float* __restrict__ W,
                               const float* __restrict__ bias,
                               float* __restrict__ Y,
                               int C, int OC,
                               long xbs, long ybs, long wbs,
                               int relu, float* __restrict__ msum)
{
    __shared__ float Xs[16 * 128];
    __shared__ float Wsd[16 * 128];   // W duplicated: [cc][oo*2 + {0,1}] both = W[oc,cc]

    const int P = PP;
    int b = blockIdx.z;
    const float* Xb = X + (long)b * xbs;
    const float* Wp = W + (long)b * wbs;

    int p0  = blockIdx.x * 128;
    int oc0 = blockIdx.y * 64;
    int tx = threadIdx.x, ty = threadIdx.y;
    int t = ty * 16 + tx;

    float4* Xs4 = reinterpret_cast<float4*>(Xs);
    const ulonglong2* XsL = reinterpret_cast<const ulonglong2*>(Xs);
    const ulonglong2* WsL = reinterpret_cast<const ulonglong2*>(Wsd);

    u64 acc[4][4];
#pragma unroll
    for (int j = 0; j < 4; j++)
#pragma unroll
        for (int i = 0; i < 4; i++) acc[j][i] = 0ULL;

    for (int c0 = 0; c0 < C; c0 += 16) {
        // Xs: 512 float4, lane-major over px -> STS conflict-free, LDG coalesced
#pragma unroll
        for (int i = t; i < 512; i += 256) {
            int cc = i >> 5, q = i & 31;
            Xs4[cc * 32 + q] =
                reinterpret_cast<const float4*>(Xb + (long)(c0 + cc) * P + p0)[q];
        }
        // Wsd: 2048 floats; duplicate slot pairs, consecutive t -> consecutive addr
#pragma unroll
        for (int i = t; i < 2048; i += 256) {
            int oo = (i >> 1) & 63, cc = i >> 7;
            int oc = oc0 + oo;
            Wsd[cc * 128 + (i & 127)] = (oc < OC) ? Wp[(long)oc * C + c0 + cc] : 0.f;
        }
        __syncthreads();
#pragma unroll
        for (int cc = 0; cc < 16; cc++) {
            ulonglong2 xa  = XsL[cc * 32 + tx];        // px tx*4..+3  (2 pairs)
            ulonglong2 xb2 = XsL[cc * 32 + 16 + tx];   // px 64+tx*4..+3
            ulonglong2 w01 = WsL[cc * 32 + ty * 2];    // (w0,w0),(w1,w1)
            ulonglong2 w23 = WsL[cc * 32 + ty * 2 + 1];// (w2,w2),(w3,w3)
            fma2(acc[0][0], xa.x,  w01.x); fma2(acc[0][1], xa.y,  w01.x);
            fma2(acc[0][2], xb2.x, w01.x); fma2(acc[0][3], xb2.y, w01.x);
            fma2(acc[1][0], xa.x,  w01.y); fma2(acc[1][1], xa.y,  w01.y);
            fma2(acc[1][2], xb2.x, w01.y); fma2(acc[1][3], xb2.y, w01.y);
            fma2(acc[2][0], xa.x,  w23.x); fma2(acc[2][1], xa.y,  w23.x);
            fma2(acc[2][2], xb2.x, w23.x); fma2(acc[2][3], xb2.y, w23.x);
            fma2(acc[3][0], xa.x,  w23.y); fma2(acc[3][1], xa.y,  w23.y);
            fma2(acc[3][2], xb2.x, w23.y); fma2(acc[3][3], xb2.y, w23.y);
        }
        __syncthreads();
    }

    if (msum == nullptr) {
        float* Yb = Y + (long)b * ybs;
#pragma unroll
        for (int j = 0; j < 4; j++) {
            int oc = oc0 + ty * 4 + j;
            if (oc < OC) {
                float bb = bias[oc];
                float v[8];
#pragma unroll
                for (int i = 0; i < 4; i++) {
                    float2 f = unpack2(acc[j][i]);
                    v[2 * i]     = f.x + bb;
                    v[2 * i + 1] = f.y + bb;
                }
                if (relu) {
#pragma unroll
                    for (int i = 0; i < 8; i++) v[i] = fmaxf(v[i], 0.f);
                }
                float* yp = Yb + (long)oc * P + p0 + tx * 4;
                *reinterpret_cast<float4*>(yp)      = make_float4(v[0], v[1], v[2], v[3]);
                *reinterpret_cast<float4*>(yp + 64) = make_float4(v[4], v[5], v[6], v[7]);
            }
        }
    } else {
        // mean mode (OC==64): relu then partial sum over the 128 px of this tile
        __syncthreads();
        float* red = Xs;     // reuse smem: [64 oc][16 tx]
#pragma unroll
        for (int j = 0; j < 4; j++) {
            float bb = bias[oc0 + ty * 4 + j];
            float s = 0.f;
#pragma unroll
            for (int i = 0; i < 4; i++) {
                float2 f = unpack2(acc[j][i]);
                s += fmaxf(f.x + bb, 0.f) + fmaxf(f.y + bb, 0.f);
            }
            red[(ty * 4 + j) * 16 + tx] = s;
        }
        __syncthreads();
        if (t < 64) {
            float s = 0.f;
#pragma unroll
            for (int i = 0; i < 16; i++) s += red[t * 16 + i];
            msum[((long)b * 64 + t) * gridDim.x + blockIdx.x] = s;
        }
    }
}

// ---------------- finish mean: att[b,o] = sum(partials)/PP ----------------
__global__ void mean_finish_kernel(const float* __restrict__ msum, float* __restrict__ att)
{
    int o = blockIdx.x, b = blockIdx.y;
    const float* p = msum + ((long)b * 64 + o) * PTILES;
    float s = 0.f;
    for (int i = threadIdx.x; i < PTILES; i += 32) s += p[i];
#pragma unroll
    for (int off = 16; off > 0; off >>= 1) s += __shfl_xor_sync(0xffffffff, s, off);
    if (threadIdx.x == 0) att[b * 64 + o] = s / (float)PP;
}

// ---------------- modulated deformable conv ----------------
template <int KK>
__global__ void mdcn_kernel(const float* __restrict__ xin,
                            const float* __restrict__ om,
                            const float* __restrict__ w,
                            const float* __restrict__ bias,
                            float* __restrict__ out,
                            int branch)
{
    constexpr int K  = KK * KK;
    constexpr int CK = INC * K;
    __shared__ float Ws[CK][64];

    int tid = threadIdx.x;
    for (int i = tid; i < CK * 64; i += blockDim.x) {
        int ck = i >> 6, o = i & 63;
        Ws[ck][o] = w[o * CK + ck];
    }
    __syncthreads();

    int p = blockIdx.x * blockDim.x + tid;
    int b = blockIdx.y;
    if (p >= PP) return;
    int h  = p / WW;
    int wx = p - h * WW;
    const int pad = KK / 2;

    const float* omb = om + (long)b * (3 * CK) * PP;
    const float* xb  = xin + (long)b * INC * PP;

    u64 acc[32];
#pragma unroll
    for (int o = 0; o < 32; o++) acc[o] = 0ULL;

    for (int c = 0; c < INC; c++) {
        const float* xc = xb + c * PP;
#pragma unroll
        for (int kk = 0; kk < K; kk++) {
            int ck = c * K + kk;
            float oy   = omb[(long)(2 * ck + 0) * PP + p];
            float ox   = omb[(long)(2 * ck + 1) * PP + p];
            float mraw = omb[(long)(2 * CK + ck) * PP + p];
            float m = 1.f / (1.f + __expf(-mraw));

            float py = oy + (float)(kk / KK) + (float)h - (float)pad;
            float px = ox + (float)(kk % KK) + (float)wx - (float)pad;
            float fy0 = floorf(py), fx0 = floorf(px);
            float wy = py - fy0, wxx = px - fx0;
            int iy0 = (int)fy0, ix0 = (int)fx0;
            int iy1 = iy0 + 1, ix1 = ix0 + 1;

            bool vy0 = (iy0 >= 0) & (iy0 < HH);
            bool vy1 = (iy1 >= 0) & (iy1 < HH);
            bool vx0 = (ix0 >= 0) & (ix0 < WW);
            bool vx1 = (ix1 >= 0) & (ix1 < WW);
            int cy0 = min(max(iy0, 0), HH - 1);
            int cy1 = min(max(iy1, 0), HH - 1);
            int cx0 = min(max(ix0, 0), WW - 1);
            int cx1 = min(max(ix1, 0), WW - 1);

            float v00 = (vy0 & vx0) ? xc[cy0 * WW + cx0] : 0.f;
            float v01 = (vy0 & vx1) ? xc[cy0 * WW + cx1] : 0.f;
            float v10 = (vy1 & vx0) ? xc[cy1 * WW + cx0] : 0.f;
            float v11 = (vy1 & vx1) ? xc[cy1 * WW + cx1] : 0.f;

            float s = (v00 * (1.f - wy) * (1.f - wxx) +
                       v01 * (1.f - wy) * wxx +
                       v10 * wy * (1.f - wxx) +
                       v11 * wy * wxx) * m;

            u64 s2 = pack2(s);
            const ulonglong2* wr = reinterpret_cast<const ulonglong2*>(&Ws[ck][0]);
#pragma unroll
            for (int j = 0; j < 16; j++) {
                ulonglong2 w2 = wr[j];
                fma2(acc[2 * j],     s2, w2.x);
                fma2(acc[2 * j + 1], s2, w2.y);
            }
        }
    }

    float* ob = out + ((long)(b * 3 + branch) * 64) * PP + p;
#pragma unroll
    for (int j = 0; j < 32; j++) {
        float2 f = unpack2(acc[j]);
        ob[(long)(2 * j) * PP]     = fmaxf(f.x + bias[2 * j], 0.f);
        ob[(long)(2 * j + 1) * PP] = fmaxf(f.y + bias[2 * j + 1], 0.f);
    }
}

// ---------------- tiny head: fc -> relu -> fcs -> atts; fold atts into conv_w ----------------
__global__ void head_kernel(const float* __restrict__ att,
                            const float* __restrict__ fc_w, const float* __restrict__ fc_b,
                            const float* __restrict__ fw0, const float* __restrict__ fb0,
                            const float* __restrict__ fw1, const float* __restrict__ fb1,
                            const float* __restrict__ fw2, const float* __restrict__ fb2,
                            const float* __restrict__ conv_w,
                            float* __restrict__ Wb, float* __restrict__ atts)
{
    __shared__ float a2[BN][32];
    int t = threadIdx.x;
    if (t < BN * 32) {
        int b = t >> 5, o = t & 31;
        float s = fc_b[o];
        for (int c = 0; c < 64; c++) s += fc_w[o * 64 + c] * att[b * 64 + c];
        a2[b][o] = fmaxf(s, 0.f);
    }
    __syncthreads();
    __shared__ float as[BN][192];
    for (int idx = t; idx < BN * 192; idx += blockDim.x) {
        int b = idx / 192, r = idx % 192;
        int i = r / 64, o = r % 64;
        const float* fw = (i == 0) ? fw0 : ((i == 1) ? fw1 : fw2);
        const float* fb = (i == 0) ? fb0 : ((i == 1) ? fb1 : fb2);
        float s = fb[o];
        for (int c = 0; c < 32; c++) s += fw[o * 32 + c] * a2[b][c];
        as[b][r] = s;
        atts[idx] = s;
    }
    __syncthreads();
    for (int idx = t; idx < BN * 64 * 192; idx += blockDim.x) {
        int b  = idx / (64 * 192);
        int r  = idx % (64 * 192);
        int o  = r / 192;
        int tc = r % 192;
        Wb[idx] = conv_w[o * 192 + tc] * as[b][tc];
    }
}

// ---------------- launch ----------------
extern "C" void kernel_launch(void* const* d_in, const int* in_sizes, int n_in,
                              void* d_out, int out_size)
{
    (void)in_sizes; (void)n_in; (void)out_size;
    const float* fea    = (const float*)d_in[0];
    const float* inputs = (const float*)d_in[1];
    const float* attn_w = (const float*)d_in[20];
    const float* attn_b = (const float*)d_in[21];
    const float* fc_w   = (const float*)d_in[22];
    const float* fc_b   = (const float*)d_in[23];
    const float* conv_w = (const float*)d_in[30];
    const float* conv_b = (const float*)d_in[31];

    float *dw, *om, *stack, *attp, *att, *atts, *Wb;
    cudaGetSymbolAddress((void**)&dw, g_dw);
    cudaGetSymbolAddress((void**)&om, g_om);
    cudaGetSymbolAddress((void**)&stack, g_stack);
    cudaGetSymbolAddress((void**)&attp, g_attp);
    cudaGetSymbolAddress((void**)&att, g_att);
    cudaGetSymbolAddress((void**)&atts, g_atts);
    cudaGetSymbolAddress((void**)&Wb, g_Wb);

    dim3 gthr(16, 16);

    for (int i = 0; i < 3; i++) {
        const float* dww  = (const float*)d_in[2 + 6 * i];
        const float* dwb  = (const float*)d_in[3 + 6 * i];
        const float* pww  = (const float*)d_in[4 + 6 * i];
        const float* pwb  = (const float*)d_in[5 + 6 * i];
        const float* dcnw = (const float*)d_in[6 + 6 * i];
        const float* dcnb = (const float*)d_in[7 + 6 * i];
        int k  = 2 * i + 1;
        int oc = INC * 3 * k * k;   // 21, 189, 525

        int total4 = BN * CF * PP / 4;
        int blocks = (total4 + 255) / 256;
        if (i == 0) dw_conv_kernel<1><<<blocks, 256>>>(fea, dww, dwb, dw);
        if (i == 1) dw_conv_kernel<3><<<blocks, 256>>>(fea, dww, dwb, dw);
        if (i == 2) dw_conv_kernel<5><<<blocks, 256>>>(fea, dww, dwb, dw);

        dim3 ggrid(PTILES, (oc + 63) / 64, BN);
        pw_gemm_kernel<<<ggrid, gthr>>>(dw, pww, pwb, om,
                                        64, oc,
                                        (long)64 * PP, (long)oc * PP, 0, 0, nullptr);

        dim3 mgrid(PP / 128, BN);
        if (i == 0) mdcn_kernel<1><<<mgrid, 128>>>(inputs, om, dcnw, dcnb, stack, i);
        if (i == 1) mdcn_kernel<3><<<mgrid, 128>>>(inputs, om, dcnw, dcnb, stack, i);
        if (i == 2) mdcn_kernel<5><<<mgrid, 128>>>(inputs, om, dcnw, dcnb, stack, i);
    }

    // attention: relu(pw(stack, attn_w)) -> mean (fused partial sums)
    dim3 agrid(PTILES, 1, BN);
    pw_gemm_kernel<<<agrid, gthr>>>(stack, attn_w, attn_b, nullptr,
                                    192, 64,
                                    (long)192 * PP, 0, 0, 1, attp);
    dim3 rgrid(64, BN);
    mean_finish_kernel<<<rgrid, 32>>>(attp, att);

    head_kernel<<<1, 256>>>(att, fc_w, fc_b,
                            (const float*)d_in[24], (const float*)d_in[25],
                            (const float*)d_in[26], (const float*)d_in[27],
                            (const float*)d_in[28], (const float*)d_in[29],
                            conv_w, Wb, atts);

    // final: relu(pw(stack, Wb)) with atts folded into per-batch weights
    pw_gemm_kernel<<<agrid, gthr>>>(stack, Wb, conv_b, (float*)d_out,
                                    192, 64,
                                    (long)192 * PP, (long)64 * PP, (long)64 * 192, 1, nullptr);
}

// round 6
// speedup vs baseline: 1.0765x; 1.0765x over previous
#include <cuda_runtime.h>
#include <cuda_bf16.h>
#include <math.h>

#define BN 4
#define HH 192
#define WW 192
#define PP (HH*WW)           // 36864
#define CF 64
#define ONC 64
#define INC 7
#define PTILES (PP/128)      // 288

// ---------------- scratch (device globals; no runtime allocation) ----------------
__device__ float g_dw[BN * CF * PP];            // depthwise output
__device__ float g_om[BN * 525 * PP];           // offset/mask (max k=5)
__device__ float g_stack[BN * 3 * ONC * PP];    // stacked branch outputs
__device__ float g_attp[BN * ONC * PTILES];     // attn partial sums
__device__ float g_att[BN * ONC];
__device__ float g_atts[BN * 3 * ONC];
__device__ float g_Wt[65536];                   // transposed weights: b0@0(64x64), b1@4096(64x192), b2@16384(64x576), attn@53248(192x64)
__device__ float g_Wbt[BN * 3 * ONC * ONC];     // per-batch folded final weights, [b][tc][o]

#define WT_B0   0
#define WT_B1   4096
#define WT_B2   16384
#define WT_ATT  53248

// ---------------- W transpose (+ zero pad): wt[c*OCpad+oc] = w[oc*C+c] ----------------
__global__ void transposeW_kernel(const float* __restrict__ w, float* __restrict__ wt,
                                  int OC, int OCpad, int C)
{
    int idx = blockIdx.x * blockDim.x + threadIdx.x;
    if (idx >= C * OCpad) return;
    int c = idx / OCpad, oc = idx % OCpad;
    wt[idx] = (oc < OC) ? w[oc * C + c] : 0.f;
}

// ---------------- depthwise conv (k = 1,3,5, SAME padding), 4 px / thread ----------------
template <int KK>
__global__ void dw_conv_kernel(const float* __restrict__ x,
                               const float* __restrict__ w,
                               const float* __restrict__ bias,
                               float* __restrict__ y)
{
    const int P4 = PP / 4;
    int idx = blockIdx.x * blockDim.x + threadIdx.x;
    if (idx >= BN * CF * P4) return;
    int p4 = idx % P4;
    int c  = (idx / P4) % CF;
    int b  = idx / (CF * P4);
    int p  = p4 * 4;
    int h  = p / WW;
    int x0 = p - h * WW;
    const int pad = KK / 2;
    const float* xp = x + ((long)(b * CF + c)) * PP;
    const float* wp = w + c * KK * KK;

    float acc[4];
    float bb = bias[c];
#pragma unroll
    for (int i = 0; i < 4; i++) acc[i] = bb;

    bool inter = (h >= pad) && (h < HH - pad) && (x0 >= pad) && (x0 + 3 + pad < WW);

#pragma unroll
    for (int ky = 0; ky < KK; ky++) {
        int yy = h + ky - pad;
        const float* r = xp + yy * WW + x0 - pad;
        float v[KK + 3];
        if (inter) {
#pragma unroll
            for (int m = 0; m < KK + 3; m++) v[m] = r[m];
        } else {
            bool vy = (yy >= 0) && (yy < HH);
#pragma unroll
            for (int m = 0; m < KK + 3; m++) {
                int xx = x0 - pad + m;
                v[m] = (vy && xx >= 0 && xx < WW) ? xp[yy * WW + xx] : 0.f;
            }
        }
#pragma unroll
        for (int kx = 0; kx < KK; kx++) {
            float wv = wp[ky * KK + kx];
#pragma unroll
            for (int i = 0; i < 4; i++) acc[i] += v[i + kx] * wv;
        }
    }
    float4 o4 = make_float4(acc[0], acc[1], acc[2], acc[3]);
    *reinterpret_cast<float4*>(y + (long)idx * 4) = o4;
}

// ---------------- pointwise GEMM: Y[b,oc,p] = sum_c Wt[c,oc]*X[b,c,p] + bias ----------------
// 256 threads, 128-px tile, 8px x 4oc micro-tile, coalesced Wt loads.
// Path A (C==64): X loaded once into smem, loop over OCpad/64 oc-tiles.
// Path B (OC==64): single oc tile, chunk over C by 64.
__global__ void pw_gemm_kernel(const float* __restrict__ X,
                               const float* __restrict__ Wt,
                               const float* __restrict__ bias,
                               float* __restrict__ Y,
                               int C, int OC, int OCpad,
                               long xbs, long ybs, long wbs,
                               int relu, float* __restrict__ msum)
{
    __shared__ float Xs[64 * 128];   // 32 KB
    __shared__ float Ws[64 * 64];    // 16 KB ([cc][oo])

    const int P = PP;
    int b = blockIdx.z;
    const float* Xb = X + (long)b * xbs;
    const float* Wp = Wt + (long)b * wbs;

    int p0 = blockIdx.x * 128;
    int tx = threadIdx.x, ty = threadIdx.y;
    int t = ty * 16 + tx;

    float4* Xs4 = reinterpret_cast<float4*>(Xs);
    const float4* Ws4 = reinterpret_cast<const float4*>(Ws);

    if (C == 64) {
        // ---- Path A: X resident, loop oc tiles ----
#pragma unroll
        for (int i = t; i < 2048; i += 256) {
            int cc = i >> 5, q = i & 31;
            Xs4[i] = reinterpret_cast<const float4*>(Xb + (long)cc * P + p0)[q];
        }
        __syncthreads();

        int nT = OCpad >> 6;
        for (int ocT = 0; ocT < nT; ocT++) {
            int oc0 = ocT * 64;
            // coalesced W fill: consecutive t -> consecutive oo
#pragma unroll
            for (int i = t; i < 4096; i += 256) {
                int cc = i >> 6, oo = i & 63;
                Ws[i] = Wp[(long)cc * OCpad + oc0 + oo];
            }
            __syncthreads();

            float acc[4][8] = {};
#pragma unroll
            for (int cc = 0; cc < 64; cc++) {
                float4 xa  = Xs4[cc * 32 + tx];
                float4 xb2 = Xs4[cc * 32 + 16 + tx];
                float4 wv  = Ws4[cc * 16 + ty];
                float xv[8] = {xa.x, xa.y, xa.z, xa.w, xb2.x, xb2.y, xb2.z, xb2.w};
                float wa[4] = {wv.x, wv.y, wv.z, wv.w};
#pragma unroll
                for (int j = 0; j < 4; j++)
#pragma unroll
                    for (int i = 0; i < 8; i++)
                        acc[j][i] += xv[i] * wa[j];
            }

            float* Yb = Y + (long)b * ybs;
#pragma unroll
            for (int j = 0; j < 4; j++) {
                int oc = oc0 + ty * 4 + j;
                if (oc < OC) {
                    float bb = bias[oc];
                    float v[8];
#pragma unroll
                    for (int i = 0; i < 8; i++) {
                        v[i] = acc[j][i] + bb;
                        if (relu) v[i] = fmaxf(v[i], 0.f);
                    }
                    float* yp = Yb + (long)oc * P + p0 + tx * 4;
                    *reinterpret_cast<float4*>(yp)      = make_float4(v[0], v[1], v[2], v[3]);
                    *reinterpret_cast<float4*>(yp + 64) = make_float4(v[4], v[5], v[6], v[7]);
                }
            }
            __syncthreads();
        }
    } else {
        // ---- Path B: OC==64, chunk over C ----
        float acc[4][8] = {};
        for (int c0 = 0; c0 < C; c0 += 64) {
#pragma unroll
            for (int i = t; i < 2048; i += 256) {
                int cc = i >> 5, q = i & 31;
                Xs4[i] = reinterpret_cast<const float4*>(Xb + (long)(c0 + cc) * P + p0)[q];
            }
#pragma unroll
            for (int i = t; i < 4096; i += 256) {
                int cc = i >> 6, oo = i & 63;
                Ws[i] = Wp[(long)(c0 + cc) * OCpad + oo];
            }
            __syncthreads();
#pragma unroll
            for (int cc = 0; cc < 64; cc++) {
                float4 xa  = Xs4[cc * 32 + tx];
                float4 xb2 = Xs4[cc * 32 + 16 + tx];
                float4 wv  = Ws4[cc * 16 + ty];
                float xv[8] = {xa.x, xa.y, xa.z, xa.w, xb2.x, xb2.y, xb2.z, xb2.w};
                float wa[4] = {wv.x, wv.y, wv.z, wv.w};
#pragma unroll
                for (int j = 0; j < 4; j++)
#pragma unroll
                    for (int i = 0; i < 8; i++)
                        acc[j][i] += xv[i] * wa[j];
            }
            __syncthreads();
        }

        if (msum == nullptr) {
            float* Yb = Y + (long)b * ybs;
#pragma unroll
            for (int j = 0; j < 4; j++) {
                int oc = ty * 4 + j;
                float bb = bias[oc];
                float v[8];
#pragma unroll
                for (int i = 0; i < 8; i++) {
                    v[i] = acc[j][i] + bb;
                    if (relu) v[i] = fmaxf(v[i], 0.f);
                }
                float* yp = Yb + (long)oc * P + p0 + tx * 4;
                *reinterpret_cast<float4*>(yp)      = make_float4(v[0], v[1], v[2], v[3]);
                *reinterpret_cast<float4*>(yp + 64) = make_float4(v[4], v[5], v[6], v[7]);
            }
        } else {
            // mean mode: relu then partial sum over this tile's 128 px
            float* red = Xs;     // [64 oc][16 tx]
#pragma unroll
            for (int j = 0; j < 4; j++) {
                float bb = bias[ty * 4 + j];
                float s = 0.f;
#pragma unroll
                for (int i = 0; i < 8; i++) s += fmaxf(acc[j][i] + bb, 0.f);
                red[(ty * 4 + j) * 16 + tx] = s;
            }
            __syncthreads();
            if (t < 64) {
                float s = 0.f;
#pragma unroll
                for (int i = 0; i < 16; i++) s += red[t * 16 + i];
                msum[((long)b * 64 + t) * gridDim.x + blockIdx.x] = s;
            }
        }
    }
}

// ---------------- finish mean: att[b,o] = sum(partials)/PP ----------------
__global__ void mean_finish_kernel(const float* __restrict__ msum, float* __restrict__ att)
{
    int o = blockIdx.x, b = blockIdx.y;
    const float* p = msum + ((long)b * 64 + o) * PTILES;
    float s = 0.f;
    for (int i = threadIdx.x; i < PTILES; i += 32) s += p[i];
#pragma unroll
    for (int off = 16; off > 0; off >>= 1) s += __shfl_xor_sync(0xffffffff, s, off);
    if (threadIdx.x == 0) att[b * 64 + o] = s / (float)PP;
}

// ---------------- modulated deformable conv ----------------
template <int KK>
__global__ void mdcn_kernel(const float* __restrict__ xin,
                            const float* __restrict__ om,
                            const float* __restrict__ w,
                            const float* __restrict__ bias,
                            float* __restrict__ out,
                            int branch)
{
    constexpr int K  = KK * KK;
    constexpr int CK = INC * K;
    __shared__ float Ws[CK][64];

    int tid = threadIdx.x;
    for (int i = tid; i < CK * 64; i += blockDim.x) {
        int ck = i >> 6, o = i & 63;
        Ws[ck][o] = w[o * CK + ck];
    }
    __syncthreads();

    int p = blockIdx.x * blockDim.x + tid;
    int b = blockIdx.y;
    if (p >= PP) return;
    int h  = p / WW;
    int wx = p - h * WW;
    const int pad = KK / 2;

    const float* omb = om + (long)b * (3 * CK) * PP;
    const float* xb  = xin + (long)b * INC * PP;

    float acc[64];
#pragma unroll
    for (int o = 0; o < 64; o++) acc[o] = 0.f;

    for (int c = 0; c < INC; c++) {
        const float* xc = xb + c * PP;
#pragma unroll
        for (int kk = 0; kk < K; kk++) {
            int ck = c * K + kk;
            float oy   = omb[(long)(2 * ck + 0) * PP + p];
            float ox   = omb[(long)(2 * ck + 1) * PP + p];
            float mraw = omb[(long)(2 * CK + ck) * PP + p];
            float m = 1.f / (1.f + __expf(-mraw));

            float py = oy + (float)(kk / KK) + (float)h - (float)pad;
            float px = ox + (float)(kk % KK) + (float)wx - (float)pad;
            float fy0 = floorf(py), fx0 = floorf(px);
            float wy = py - fy0, wxx = px - fx0;
            int iy0 = (int)fy0, ix0 = (int)fx0;
            int iy1 = iy0 + 1, ix1 = ix0 + 1;

            bool vy0 = (iy0 >= 0) & (iy0 < HH);
            bool vy1 = (iy1 >= 0) & (iy1 < HH);
            bool vx0 = (ix0 >= 0) & (ix0 < WW);
            bool vx1 = (ix1 >= 0) & (ix1 < WW);
            int cy0 = min(max(iy0, 0), HH - 1);
            int cy1 = min(max(iy1, 0), HH - 1);
            int cx0 = min(max(ix0, 0), WW - 1);
            int cx1 = min(max(ix1, 0), WW - 1);

            float v00 = (vy0 & vx0) ? xc[cy0 * WW + cx0] : 0.f;
            float v01 = (vy0 & vx1) ? xc[cy0 * WW + cx1] : 0.f;
            float v10 = (vy1 & vx0) ? xc[cy1 * WW + cx0] : 0.f;
            float v11 = (vy1 & vx1) ? xc[cy1 * WW + cx1] : 0.f;

            float s = (v00 * (1.f - wy) * (1.f - wxx) +
                       v01 * (1.f - wy) * wxx +
                       v10 * wy * (1.f - wxx) +
                       v11 * wy * wxx) * m;

            const float4* wr = reinterpret_cast<const float4*>(&Ws[ck][0]);
#pragma unroll
            for (int j = 0; j < 16; j++) {
                float4 w4 = wr[j];
                acc[4 * j + 0] += s * w4.x;
                acc[4 * j + 1] += s * w4.y;
                acc[4 * j + 2] += s * w4.z;
                acc[4 * j + 3] += s * w4.w;
            }
        }
    }

    float* ob = out + ((long)(b * 3 + branch) * 64) * PP + p;
#pragma unroll
    for (int o = 0; o < 64; o++)
        ob[(long)o * PP] = fmaxf(acc[o] + bias[o], 0.f);
}

// ---------------- tiny head: fc -> relu -> fcs -> atts; fold atts into transposed conv_w ----------------
__global__ void head_kernel(const float* __restrict__ att,
                            const float* __restrict__ fc_w, const float* __restrict__ fc_b,
                            const float* __restrict__ fw0, const float* __restrict__ fb0,
                            const float* __restrict__ fw1, const float* __restrict__ fb1,
                            const float* __restrict__ fw2, const float* __restrict__ fb2,
                            const float* __restrict__ conv_w,
                            float* __restrict__ Wbt, float* __restrict__ atts)
{
    __shared__ float a2[BN][32];
    int t = threadIdx.x;
    if (t < BN * 32) {
        int b = t >> 5, o = t & 31;
        float s = fc_b[o];
        for (int c = 0; c < 64; c++) s += fc_w[o * 64 + c] * att[b * 64 + c];
        a2[b][o] = fmaxf(s, 0.f);
    }
    __syncthreads();
    __shared__ float as[BN][192];
    for (int idx = t; idx < BN * 192; idx += blockDim.x) {
        int b = idx / 192, r = idx % 192;
        int i = r / 64, o = r % 64;
        const float* fw = (i == 0) ? fw0 : ((i == 1) ? fw1 : fw2);
        const float* fb = (i == 0) ? fb0 : ((i == 1) ? fb1 : fb2);
        float s = fb[o];
        for (int c = 0; c < 32; c++) s += fw[o * 32 + c] * a2[b][c];
        as[b][r] = s;
        atts[idx] = s;
    }
    __syncthreads();
    // Wbt[b][tc][o] = conv_w[o,tc] * as[b][tc]  (transposed for the GEMM)
    for (int idx = t; idx < BN * 192 * 64; idx += blockDim.x) {
        int b  = idx / (192 * 64);
        int r  = idx % (192 * 64);
        int tc = r / 64;
        int o  = r % 64;
        Wbt[idx] = conv_w[o * 192 + tc] * as[b][tc];
    }
}

// ---------------- launch ----------------
extern "C" void kernel_launch(void* const* d_in, const int* in_sizes, int n_in,
                              void* d_out, int out_size)
{
    (void)in_sizes; (void)n_in; (void)out_size;
    const float* fea    = (const float*)d_in[0];
    const float* inputs = (const float*)d_in[1];
    const float* attn_w = (const float*)d_in[20];
    const float* attn_b = (const float*)d_in[21];
    const float* fc_w   = (const float*)d_in[22];
    const float* fc_b   = (const float*)d_in[23];
    const float* conv_w = (const float*)d_in[30];
    const float* conv_b = (const float*)d_in[31];

    float *dw, *om, *stack, *attp, *att, *atts, *Wt, *Wbt;
    cudaGetSymbolAddress((void**)&dw, g_dw);
    cudaGetSymbolAddress((void**)&om, g_om);
    cudaGetSymbolAddress((void**)&stack, g_stack);
    cudaGetSymbolAddress((void**)&attp, g_attp);
    cudaGetSymbolAddress((void**)&att, g_att);
    cudaGetSymbolAddress((void**)&atts, g_atts);
    cudaGetSymbolAddress((void**)&Wt, g_Wt);
    cudaGetSymbolAddress((void**)&Wbt, g_Wbt);

    const int wtOff[3]  = {WT_B0, WT_B1, WT_B2};
    const int ocPad[3]  = {64, 192, 576};

    dim3 gthr(16, 16);

    // weight transposes (tiny)
    for (int i = 0; i < 3; i++) {
        const float* pww = (const float*)d_in[4 + 6 * i];
        int k = 2 * i + 1;
        int oc = INC * 3 * k * k;
        int n = 64 * ocPad[i];
        transposeW_kernel<<<(n + 255) / 256, 256>>>(pww, Wt + wtOff[i], oc, ocPad[i], 64);
    }
    transposeW_kernel<<<(192 * 64 + 255) / 256, 256>>>(attn_w, Wt + WT_ATT, 64, 64, 192);

    for (int i = 0; i < 3; i++) {
        const float* dww  = (const float*)d_in[2 + 6 * i];
        const float* dwb  = (const float*)d_in[3 + 6 * i];
        const float* pwb  = (const float*)d_in[5 + 6 * i];
        const float* dcnw = (const float*)d_in[6 + 6 * i];
        const float* dcnb = (const float*)d_in[7 + 6 * i];
        int k  = 2 * i + 1;
        int oc = INC * 3 * k * k;   // 21, 189, 525

        int total4 = BN * CF * PP / 4;
        int blocks = (total4 + 255) / 256;
        if (i == 0) dw_conv_kernel<1><<<blocks, 256>>>(fea, dww, dwb, dw);
        if (i == 1) dw_conv_kernel<3><<<blocks, 256>>>(fea, dww, dwb, dw);
        if (i == 2) dw_conv_kernel<5><<<blocks, 256>>>(fea, dww, dwb, dw);

        dim3 ggrid(PTILES, 1, BN);
        pw_gemm_kernel<<<ggrid, gthr>>>(dw, Wt + wtOff[i], pwb, om,
                                        64, oc, ocPad[i],
                                        (long)64 * PP, (long)oc * PP, 0, 0, nullptr);

        dim3 mgrid(PP / 128, BN);
        if (i == 0) mdcn_kernel<1><<<mgrid, 128>>>(inputs, om, dcnw, dcnb, stack, i);
        if (i == 1) mdcn_kernel<3><<<mgrid, 128>>>(inputs, om, dcnw, dcnb, stack, i);
        if (i == 2) mdcn_kernel<5><<<mgrid, 128>>>(inputs, om, dcnw, dcnb, stack, i);
    }

    // attention: relu(pw(stack, attn_w)) -> mean (fused partial sums)
    dim3 agrid(PTILES, 1, BN);
    pw_gemm_kernel<<<agrid, gthr>>>(stack, Wt + WT_ATT, attn_b, nullptr,
                                    192, 64, 64,
                                    (long)192 * PP, 0, 0, 1, attp);
    dim3 rgrid(64, BN);
    mean_finish_kernel<<<rgrid, 32>>>(attp, att);

    head_kernel<<<1, 256>>>(att, fc_w, fc_b,
                            (const float*)d_in[24], (const float*)d_in[25],
                            (const float*)d_in[26], (const float*)d_in[27],
                            (const float*)d_in[28], (const float*)d_in[29],
                            conv_w, Wbt, atts);

    // final: relu(pw(stack, Wbt)) with atts folded into per-batch transposed weights
    pw_gemm_kernel<<<agrid, gthr>>>(stack, Wbt, conv_b, (float*)d_out,
                                    192, 64, 64,
                                    (long)192 * PP, (long)64 * PP, (long)192 * 64, 1, nullptr);
}

// round 8
// speedup vs baseline: 1.5409x; 1.4314x over previous
#include <cuda_runtime.h>
#include <cuda_bf16.h>
#include <math.h>

#define BN 4
#define HH 192
#define WW 192
#define PP (HH*WW)           // 36864
#define CF 64
#define ONC 64
#define INC 7
#define PTILES (PP/128)      // 288

#define XSTR 136             // Xs row stride (8 mod 32 -> conflict-free A frags)
#define WSTR 72              // Ws row stride (8 mod 32 -> conflict-free B frags)
#define GEMM_SMEM ((64*XSTR + 64*WSTR) * 4)   // 53248 bytes (dynamic)

// ---------------- scratch (device globals; no runtime allocation) ----------------
__device__ float g_dw[BN * CF * PP];            // depthwise output
__device__ float g_om[BN * 525 * PP];           // offset/mask (max k=5)
__device__ float g_stack[BN * 3 * ONC * PP];    // stacked branch outputs
__device__ float g_attp[BN * ONC * PTILES];     // attn partial sums
__device__ float g_att[BN * ONC];
__device__ float g_atts[BN * 3 * ONC];
__device__ float g_Wt[65536];                   // transposed weights
__device__ float g_Wbt[BN * 3 * ONC * ONC];     // per-batch folded final weights, [b][tc][o]

#define WT_B0   0
#define WT_B1   4096
#define WT_B2   16384
#define WT_ATT  53248

__device__ __forceinline__ unsigned tf32b(float f) {
    unsigned r; asm("cvt.rna.tf32.f32 %0, %1;" : "=r"(r) : "f"(f)); return r;
}
__device__ __forceinline__ void mma8(float* d, unsigned a0, unsigned a1, unsigned a2, unsigned a3,
                                     unsigned b0, unsigned b1) {
    asm("mma.sync.aligned.m16n8k8.row.col.f32.tf32.tf32.f32 "
        "{%0,%1,%2,%3},{%4,%5,%6,%7},{%8,%9},{%0,%1,%2,%3};"
        : "+f"(d[0]), "+f"(d[1]), "+f"(d[2]), "+f"(d[3])
        : "r"(a0), "r"(a1), "r"(a2), "r"(a3), "r"(b0), "r"(b1));
}

// ---------------- W transpose (+ zero pad): wt[c*OCpad+oc] = w[oc*C+c] ----------------
__global__ void transposeW_kernel(const float* __restrict__ w, float* __restrict__ wt,
                                  int OC, int OCpad, int C)
{
    int idx = blockIdx.x * blockDim.x + threadIdx.x;
    if (idx >= C * OCpad) return;
    int c = idx / OCpad, oc = idx % OCpad;
    wt[idx] = (oc < OC) ? w[oc * C + c] : 0.f;
}

// ---------------- depthwise conv (k = 1,3,5, SAME padding), 4 px / thread ----------------
template <int KK>
__global__ void dw_conv_kernel(const float* __restrict__ x,
                               const float* __restrict__ w,
                               const float* __restrict__ bias,
                               float* __restrict__ y)
{
    const int P4 = PP / 4;
    int idx = blockIdx.x * blockDim.x + threadIdx.x;
    if (idx >= BN * CF * P4) return;
    int p4 = idx % P4;
    int c  = (idx / P4) % CF;
    int b  = idx / (CF * P4);
    int p  = p4 * 4;
    int h  = p / WW;
    int x0 = p - h * WW;
    const int pad = KK / 2;
    const float* xp = x + ((long)(b * CF + c)) * PP;
    const float* wp = w + c * KK * KK;

    float acc[4];
    float bb = bias[c];
#pragma unroll
    for (int i = 0; i < 4; i++) acc[i] = bb;

    bool inter = (h >= pad) && (h < HH - pad) && (x0 >= pad) && (x0 + 3 + pad < WW);

#pragma unroll
    for (int ky = 0; ky < KK; ky++) {
        int yy = h + ky - pad;
        const float* r = xp + yy * WW + x0 - pad;
        float v[KK + 3];
        if (inter) {
#pragma unroll
            for (int m = 0; m < KK + 3; m++) v[m] = r[m];
        } else {
            bool vy = (yy >= 0) && (yy < HH);
#pragma unroll
            for (int m = 0; m < KK + 3; m++) {
                int xx = x0 - pad + m;
                v[m] = (vy && xx >= 0 && xx < WW) ? xp[yy * WW + xx] : 0.f;
            }
        }
#pragma unroll
        for (int kx = 0; kx < KK; kx++) {
            float wv = wp[ky * KK + kx];
#pragma unroll
            for (int i = 0; i < 4; i++) acc[i] += v[i + kx] * wv;
        }
    }
    float4 o4 = make_float4(acc[0], acc[1], acc[2], acc[3]);
    *reinterpret_cast<float4*>(y + (long)idx * 4) = o4;
}

// ---------------- tf32 pointwise GEMM: Y[b,oc,p] = sum_c Wt[c,oc]*X[b,c,p] + bias ----------------
// 256 threads (8 warps), 128-px tile. Warp w covers px [w*16, w*16+16), all 64 oc of a tile.
// Dynamic smem: Xs[64*XSTR] then Ws[64*WSTR]; mean-mode red aliases Ws.
__global__ void pw_gemm_tf32_kernel(const float* __restrict__ X,
                                    const float* __restrict__ Wt,
                                    const float* __restrict__ bias,
                                    float* __restrict__ Y,
                                    int C, int OC, int OCpad,
                                    long xbs, long ybs, long wbs,
                                    int relu, float* __restrict__ msum)
{
    extern __shared__ float smem[];
    float* Xs = smem;                  // [64][XSTR]
    float* Ws = smem + 64 * XSTR;      // [64][WSTR]
    float* red = Ws;                   // mean-mode warp partials (aliases Ws, used post-compute)

    const int P = PP;
    int b = blockIdx.z;
    const float* Xb = X + (long)b * xbs;
    const float* Wp = Wt + (long)b * wbs;

    int p0 = blockIdx.x * 128;
    int t = threadIdx.x;
    int lane = t & 31, wid = t >> 5;
    int pw = wid * 16;                 // warp's px row base within tile
    int g = lane >> 2, k4 = lane & 3;  // groupID, threadID_in_group

    if (C == 64) {
        // ---- Path A: X resident, loop oc tiles ----
        for (int i = t; i < 2048; i += 256) {
            int cc = i >> 5, q = i & 31;
            float4 v = reinterpret_cast<const float4*>(Xb + (long)cc * P + p0)[q];
            float4 o;
            o.x = __uint_as_float(tf32b(v.x)); o.y = __uint_as_float(tf32b(v.y));
            o.z = __uint_as_float(tf32b(v.z)); o.w = __uint_as_float(tf32b(v.w));
            *reinterpret_cast<float4*>(&Xs[cc * XSTR + q * 4]) = o;
        }
        __syncthreads();

        int nT = OCpad >> 6;
        float* Yb = Y + (long)b * ybs;
        for (int ocT = 0; ocT < nT; ocT++) {
            int oc0 = ocT * 64;
            for (int i = t; i < 4096; i += 256) {
                int cc = i >> 6, oo = i & 63;
                Ws[cc * WSTR + oo] = __uint_as_float(tf32b(Wp[(long)cc * OCpad + oc0 + oo]));
            }
            __syncthreads();

            float acc[8][4];
#pragma unroll
            for (int nt = 0; nt < 8; nt++)
#pragma unroll
                for (int j = 0; j < 4; j++) acc[nt][j] = 0.f;

#pragma unroll
            for (int kc = 0; kc < 8; kc++) {
                int kb = kc * 8 + k4;
                unsigned a0 = __float_as_uint(Xs[kb * XSTR + pw + g]);
                unsigned a1 = __float_as_uint(Xs[kb * XSTR + pw + g + 8]);
                unsigned a2 = __float_as_uint(Xs[(kb + 4) * XSTR + pw + g]);
                unsigned a3 = __float_as_uint(Xs[(kb + 4) * XSTR + pw + g + 8]);
#pragma unroll
                for (int nt = 0; nt < 8; nt++) {
                    unsigned b0 = __float_as_uint(Ws[kb * WSTR + nt * 8 + g]);
                    unsigned b1 = __float_as_uint(Ws[(kb + 4) * WSTR + nt * 8 + g]);
                    mma8(acc[nt], a0, a1, a2, a3, b0, b1);
                }
            }

#pragma unroll
            for (int nt = 0; nt < 8; nt++) {
                int oc = oc0 + nt * 8 + k4 * 2;
                int px = p0 + pw + g;
                if (oc < OC) {
                    float bb = bias[oc];
                    float v0 = acc[nt][0] + bb, v2 = acc[nt][2] + bb;
                    if (relu) { v0 = fmaxf(v0, 0.f); v2 = fmaxf(v2, 0.f); }
                    Yb[(long)oc * P + px]     = v0;
                    Yb[(long)oc * P + px + 8] = v2;
                }
                if (oc + 1 < OC) {
                    float bb = bias[oc + 1];
                    float v1 = acc[nt][1] + bb, v3 = acc[nt][3] + bb;
                    if (relu) { v1 = fmaxf(v1, 0.f); v3 = fmaxf(v3, 0.f); }
                    Yb[(long)(oc + 1) * P + px]     = v1;
                    Yb[(long)(oc + 1) * P + px + 8] = v3;
                }
            }
            __syncthreads();
        }
    } else {
        // ---- Path B: OC==64, chunk over C ----
        float acc[8][4];
#pragma unroll
        for (int nt = 0; nt < 8; nt++)
#pragma unroll
            for (int j = 0; j < 4; j++) acc[nt][j] = 0.f;

        for (int c0 = 0; c0 < C; c0 += 64) {
            for (int i = t; i < 2048; i += 256) {
                int cc = i >> 5, q = i & 31;
                float4 v = reinterpret_cast<const float4*>(Xb + (long)(c0 + cc) * P + p0)[q];
                float4 o;
                o.x = __uint_as_float(tf32b(v.x)); o.y = __uint_as_float(tf32b(v.y));
                o.z = __uint_as_float(tf32b(v.z)); o.w = __uint_as_float(tf32b(v.w));
                *reinterpret_cast<float4*>(&Xs[cc * XSTR + q * 4]) = o;
            }
            for (int i = t; i < 4096; i += 256) {
                int cc = i >> 6, oo = i & 63;
                Ws[cc * WSTR + oo] = __uint_as_float(tf32b(Wp[(long)(c0 + cc) * OCpad + oo]));
            }
            __syncthreads();

#pragma unroll
            for (int kc = 0; kc < 8; kc++) {
                int kb = kc * 8 + k4;
                unsigned a0 = __float_as_uint(Xs[kb * XSTR + pw + g]);
                unsigned a1 = __float_as_uint(Xs[kb * XSTR + pw + g + 8]);
                unsigned a2 = __float_as_uint(Xs[(kb + 4) * XSTR + pw + g]);
                unsigned a3 = __float_as_uint(Xs[(kb + 4) * XSTR + pw + g + 8]);
#pragma unroll
                for (int nt = 0; nt < 8; nt++) {
                    unsigned b0 = __float_as_uint(Ws[kb * WSTR + nt * 8 + g]);
                    unsigned b1 = __float_as_uint(Ws[(kb + 4) * WSTR + nt * 8 + g]);
                    mma8(acc[nt], a0, a1, a2, a3, b0, b1);
                }
            }
            __syncthreads();
        }

        if (msum == nullptr) {
            float* Yb = Y + (long)b * ybs;
#pragma unroll
            for (int nt = 0; nt < 8; nt++) {
                int oc = nt * 8 + k4 * 2;
                int px = p0 + pw + g;
                float b0v = bias[oc], b1v = bias[oc + 1];
                float v0 = acc[nt][0] + b0v, v1 = acc[nt][1] + b1v;
                float v2 = acc[nt][2] + b0v, v3 = acc[nt][3] + b1v;
                if (relu) {
                    v0 = fmaxf(v0, 0.f); v1 = fmaxf(v1, 0.f);
                    v2 = fmaxf(v2, 0.f); v3 = fmaxf(v3, 0.f);
                }
                Yb[(long)oc * P + px]           = v0;
                Yb[(long)(oc + 1) * P + px]     = v1;
                Yb[(long)oc * P + px + 8]       = v2;
                Yb[(long)(oc + 1) * P + px + 8] = v3;
            }
        } else {
            // fused relu + partial mean over this tile's 128 px (red aliases Ws; compute done)
#pragma unroll
            for (int nt = 0; nt < 8; nt++) {
                int oc = nt * 8 + k4 * 2;
                float b0v = bias[oc], b1v = bias[oc + 1];
                float s0 = fmaxf(acc[nt][0] + b0v, 0.f) + fmaxf(acc[nt][2] + b0v, 0.f);
                float s1 = fmaxf(acc[nt][1] + b1v, 0.f) + fmaxf(acc[nt][3] + b1v, 0.f);
#pragma unroll
                for (int off = 4; off < 32; off <<= 1) {
                    s0 += __shfl_xor_sync(0xffffffff, s0, off);
                    s1 += __shfl_xor_sync(0xffffffff, s1, off);
                }
                if (lane < 4) {
                    red[wid * 64 + oc]     = s0;
                    red[wid * 64 + oc + 1] = s1;
                }
            }
            __syncthreads();
            if (t < 64) {
                float s = 0.f;
#pragma unroll
                for (int w = 0; w < 8; w++) s += red[w * 64 + t];
                msum[((long)b * 64 + t) * gridDim.x + blockIdx.x] = s;
            }
        }
    }
}

// ---------------- finish mean: att[b,o] = sum(partials)/PP ----------------
__global__ void mean_finish_kernel(const float* __restrict__ msum, float* __restrict__ att)
{
    int o = blockIdx.x, b = blockIdx.y;
    const float* p = msum + ((long)b * 64 + o) * PTILES;
    float s = 0.f;
    for (int i = threadIdx.x; i < PTILES; i += 32) s += p[i];
#pragma unroll
    for (int off = 16; off > 0; off >>= 1) s += __shfl_xor_sync(0xffffffff, s, off);
    if (threadIdx.x == 0) att[b * 64 + o] = s / (float)PP;
}

// ---------------- modulated deformable conv ----------------
template <int KK>
__global__ void mdcn_kernel(const float* __restrict__ xin,
                            const float* __restrict__ om,
                            const float* __restrict__ w,
                            const float* __restrict__ bias,
                            float* __restrict__ out,
                            int branch)
{
    constexpr int K  = KK * KK;
    constexpr int CK = INC * K;
    __shared__ float Ws[CK][64];

    int tid = threadIdx.x;
    for (int i = tid; i < CK * 64; i += blockDim.x) {
        int ck = i >> 6, o = i & 63;
        Ws[ck][o] = w[o * CK + ck];
    }
    __syncthreads();

    int p = blockIdx.x * blockDim.x + tid;
    int b = blockIdx.y;
    if (p >= PP) return;
    int h  = p / WW;
    int wx = p - h * WW;
    const int pad = KK / 2;

    const float* omb = om + (long)b * (3 * CK) * PP;
    const float* xb  = xin + (long)b * INC * PP;

    float acc[64];
#pragma unroll
    for (int o = 0; o < 64; o++) acc[o] = 0.f;

    for (int c = 0; c < INC; c++) {
        const float* xc = xb + c * PP;
#pragma unroll
        for (int kk = 0; kk < K; kk++) {
            int ck = c * K + kk;
            float oy   = omb[(long)(2 * ck + 0) * PP + p];
            float ox   = omb[(long)(2 * ck + 1) * PP + p];
            float mraw = omb[(long)(2 * CK + ck) * PP + p];
            float m = 1.f / (1.f + __expf(-mraw));

            float py = oy + (float)(kk / KK) + (float)h - (float)pad;
            float px = ox + (float)(kk % KK) + (float)wx - (float)pad;
            float fy0 = floorf(py), fx0 = floorf(px);
            float wy = py - fy0, wxx = px - fx0;
            int iy0 = (int)fy0, ix0 = (int)fx0;
            int iy1 = iy0 + 1, ix1 = ix0 + 1;

            bool vy0 = (iy0 >= 0) & (iy0 < HH);
            bool vy1 = (iy1 >= 0) & (iy1 < HH);
            bool vx0 = (ix0 >= 0) & (ix0 < WW);
            bool vx1 = (ix1 >= 0) & (ix1 < WW);
            int cy0 = min(max(iy0, 0), HH - 1);
            int cy1 = min(max(iy1, 0), HH - 1);
            int cx0 = min(max(ix0, 0), WW - 1);
            int cx1 = min(max(ix1, 0), WW - 1);

            float v00 = (vy0 & vx0) ? xc[cy0 * WW + cx0] : 0.f;
            float v01 = (vy0 & vx1) ? xc[cy0 * WW + cx1] : 0.f;
            float v10 = (vy1 & vx0) ? xc[cy1 * WW + cx0] : 0.f;
            float v11 = (vy1 & vx1) ? xc[cy1 * WW + cx1] : 0.f;

            float s = (v00 * (1.f - wy) * (1.f - wxx) +
                       v01 * (1.f - wy) * wxx +
                       v10 * wy * (1.f - wxx) +
                       v11 * wy * wxx) * m;

            const float4* wr = reinterpret_cast<const float4*>(&Ws[ck][0]);
#pragma unroll
            for (int j = 0; j < 16; j++) {
                float4 w4 = wr[j];
                acc[4 * j + 0] += s * w4.x;
                acc[4 * j + 1] += s * w4.y;
                acc[4 * j + 2] += s * w4.z;
                acc[4 * j + 3] += s * w4.w;
            }
        }
    }

    float* ob = out + ((long)(b * 3 + branch) * 64) * PP + p;
#pragma unroll
    for (int o = 0; o < 64; o++)
        ob[(long)o * PP] = fmaxf(acc[o] + bias[o], 0.f);
}

// ---------------- tiny head: fc -> relu -> fcs -> atts; fold atts into transposed conv_w ----------------
__global__ void head_kernel(const float* __restrict__ att,
                            const float* __restrict__ fc_w, const float* __restrict__ fc_b,
                            const float* __restrict__ fw0, const float* __restrict__ fb0,
                            const float* __restrict__ fw1, const float* __restrict__ fb1,
                            const float* __restrict__ fw2, const float* __restrict__ fb2,
                            const float* __restrict__ conv_w,
                            float* __restrict__ Wbt, float* __restrict__ atts)
{
    __shared__ float a2[BN][32];
    int t = threadIdx.x;
    if (t < BN * 32) {
        int b = t >> 5, o = t & 31;
        float s = fc_b[o];
        for (int c = 0; c < 64; c++) s += fc_w[o * 64 + c] * att[b * 64 + c];
        a2[b][o] = fmaxf(s, 0.f);
    }
    __syncthreads();
    __shared__ float as[BN][192];
    for (int idx = t; idx < BN * 192; idx += blockDim.x) {
        int b = idx / 192, r = idx % 192;
        int i = r / 64, o = r % 64;
        const float* fw = (i == 0) ? fw0 : ((i == 1) ? fw1 : fw2);
        const float* fb = (i == 0) ? fb0 : ((i == 1) ? fb1 : fb2);
        float s = fb[o];
        for (int c = 0; c < 32; c++) s += fw[o * 32 + c] * a2[b][c];
        as[b][r] = s;
        atts[idx] = s;
    }
    __syncthreads();
    // Wbt[b][tc][o] = conv_w[o,tc] * as[b][tc]  (transposed for the GEMM)
    for (int idx = t; idx < BN * 192 * 64; idx += blockDim.x) {
        int b  = idx / (192 * 64);
        int r  = idx % (192 * 64);
        int tc = r / 64;
        int o  = r % 64;
        Wbt[idx] = conv_w[o * 192 + tc] * as[b][tc];
    }
}

// ---------------- launch ----------------
extern "C" void kernel_launch(void* const* d_in, const int* in_sizes, int n_in,
                              void* d_out, int out_size)
{
    (void)in_sizes; (void)n_in; (void)out_size;
    const float* fea    = (const float*)d_in[0];
    const float* inputs = (const float*)d_in[1];
    const float* attn_w = (const float*)d_in[20];
    const float* attn_b = (const float*)d_in[21];
    const float* fc_w   = (const float*)d_in[22];
    const float* fc_b   = (const float*)d_in[23];
    const float* conv_w = (const float*)d_in[30];
    const float* conv_b = (const float*)d_in[31];

    float *dw, *om, *stack, *attp, *att, *atts, *Wt, *Wbt;
    cudaGetSymbolAddress((void**)&dw, g_dw);
    cudaGetSymbolAddress((void**)&om, g_om);
    cudaGetSymbolAddress((void**)&stack, g_stack);
    cudaGetSymbolAddress((void**)&attp, g_attp);
    cudaGetSymbolAddress((void**)&att, g_att);
    cudaGetSymbolAddress((void**)&atts, g_atts);
    cudaGetSymbolAddress((void**)&Wt, g_Wt);
    cudaGetSymbolAddress((void**)&Wbt, g_Wbt);

    // enable >48KB dynamic smem for the GEMM (host attribute call; graph-safe)
    cudaFuncSetAttribute(pw_gemm_tf32_kernel,
                         cudaFuncAttributeMaxDynamicSharedMemorySize, GEMM_SMEM);

    const int wtOff[3]  = {WT_B0, WT_B1, WT_B2};
    const int ocPad[3]  = {64, 192, 576};

    // weight transposes (tiny)
    for (int i = 0; i < 3; i++) {
        const float* pww = (const float*)d_in[4 + 6 * i];
        int k = 2 * i + 1;
        int oc = INC * 3 * k * k;
        int n = 64 * ocPad[i];
        transposeW_kernel<<<(n + 255) / 256, 256>>>(pww, Wt + wtOff[i], oc, ocPad[i], 64);
    }
    transposeW_kernel<<<(192 * 64 + 255) / 256, 256>>>(attn_w, Wt + WT_ATT, 64, 64, 192);

    for (int i = 0; i < 3; i++) {
        const float* dww  = (const float*)d_in[2 + 6 * i];
        const float* dwb  = (const float*)d_in[3 + 6 * i];
        const float* pwb  = (const float*)d_in[5 + 6 * i];
        const float* dcnw = (const float*)d_in[6 + 6 * i];
        const float* dcnb = (const float*)d_in[7 + 6 * i];
        int k  = 2 * i + 1;
        int oc = INC * 3 * k * k;   // 21, 189, 525

        int total4 = BN * CF * PP / 4;
        int blocks = (total4 + 255) / 256;
        if (i == 0) dw_conv_kernel<1><<<blocks, 256>>>(fea, dww, dwb, dw);
        if (i == 1) dw_conv_kernel<3><<<blocks, 256>>>(fea, dww, dwb, dw);
        if (i == 2) dw_conv_kernel<5><<<blocks, 256>>>(fea, dww, dwb, dw);

        dim3 ggrid(PTILES, 1, BN);
        pw_gemm_tf32_kernel<<<ggrid, 256, GEMM_SMEM>>>(dw, Wt + wtOff[i], pwb, om,
                                                       64, oc, ocPad[i],
                                                       (long)64 * PP, (long)oc * PP, 0, 0, nullptr);

        dim3 mgrid(PP / 128, BN);
        if (i == 0) mdcn_kernel<1><<<mgrid, 128>>>(inputs, om, dcnw, dcnb, stack, i);
        if (i == 1) mdcn_kernel<3><<<mgrid, 128>>>(inputs, om, dcnw, dcnb, stack, i);
        if (i == 2) mdcn_kernel<5><<<mgrid, 128>>>(inputs, om, dcnw, dcnb, stack, i);
    }

    // attention: relu(pw(stack, attn_w)) -> mean (fused partial sums)
    dim3 agrid(PTILES, 1, BN);
    pw_gemm_tf32_kernel<<<agrid, 256, GEMM_SMEM>>>(stack, Wt + WT_ATT, attn_b, nullptr,
                                                   192, 64, 64,
                                                   (long)192 * PP, 0, 0, 1, attp);
    dim3 rgrid(64, BN);
    mean_finish_kernel<<<rgrid, 32>>>(attp, att);

    head_kernel<<<1, 256>>>(att, fc_w, fc_b,
                            (const float*)d_in[24], (const float*)d_in[25],
                            (const float*)d_in[26], (const float*)d_in[27],
                            (const float*)d_in[28], (const float*)d_in[29],
                            conv_w, Wbt, atts);

    // final: relu(pw(stack, Wbt)) with atts folded into per-batch transposed weights
    pw_gemm_tf32_kernel<<<agrid, 256, GEMM_SMEM>>>(stack, Wbt, conv_b, (float*)d_out,
                                                   192, 64, 64,
                                                   (long)192 * PP, (long)64 * PP, (long)192 * 64, 1, nullptr);
}

// round 9
// speedup vs baseline: 1.6480x; 1.0695x over previous
#include <cuda_runtime.h>
#include <cuda_bf16.h>
#include <math.h>

#define BN 4
#define HH 192
#define WW 192
#define PP (HH*WW)           // 36864
#define CF 64
#define ONC 64
#define INC 7
#define PTILES (PP/128)      // 288

#define XSTR 136             // Xs row stride (8 mod 32 -> conflict-free A frags)
#define WSTR 72              // Ws row stride (8 mod 32 -> conflict-free B frags)
#define GEMM_SMEM ((64*XSTR + 64*WSTR) * 4)   // 53248 bytes (dynamic)

typedef unsigned long long u64;

__device__ __forceinline__ void fma2(u64& a, u64 x, u64 w) {
    asm("fma.rn.f32x2 %0, %1, %2, %0;" : "+l"(a) : "l"(x), "l"(w));
}
__device__ __forceinline__ u64 pack2(float s) {
    u64 r; unsigned si = __float_as_uint(s);
    asm("mov.b64 %0, {%1, %2};" : "=l"(r) : "r"(si), "r"(si));
    return r;
}
__device__ __forceinline__ float2 unpack2(u64 v) {
    float2 f; unsigned lo, hi;
    asm("mov.b64 {%0, %1}, %2;" : "=r"(lo), "=r"(hi) : "l"(v));
    f.x = __uint_as_float(lo); f.y = __uint_as_float(hi);
    return f;
}

// ---------------- scratch (device globals; no runtime allocation) ----------------
__device__ float g_dw[BN * CF * PP];            // depthwise output (k=3,5 only)
__device__ float g_om[BN * 525 * PP];           // offset/mask (max k=5)
__device__ float g_stack[BN * 3 * ONC * PP];    // stacked branch outputs
__device__ float g_attp[BN * ONC * PTILES];     // attn partial sums
__device__ float g_att[BN * ONC];
__device__ float g_atts[BN * 3 * ONC];
__device__ float g_Wt[65536];                   // transposed weights
__device__ float g_Wbt[BN * 3 * ONC * ONC];     // per-batch folded final weights, [b][tc][o]
__device__ float g_eb[64];                      // branch0 effective bias

#define WT_B0   0
#define WT_B1   4096
#define WT_B2   16384
#define WT_ATT  53248

__device__ __forceinline__ unsigned tf32b(float f) {
    unsigned r; asm("cvt.rna.tf32.f32 %0, %1;" : "=r"(r) : "f"(f)); return r;
}
__device__ __forceinline__ void mma8(float* d, unsigned a0, unsigned a1, unsigned a2, unsigned a3,
                                     unsigned b0, unsigned b1) {
    asm("mma.sync.aligned.m16n8k8.row.col.f32.tf32.tf32.f32 "
        "{%0,%1,%2,%3},{%4,%5,%6,%7},{%8,%9},{%0,%1,%2,%3};"
        : "+f"(d[0]), "+f"(d[1]), "+f"(d[2]), "+f"(d[3])
        : "r"(a0), "r"(a1), "r"(a2), "r"(a3), "r"(b0), "r"(b1));
}

// ---------------- W transpose (+ zero pad): wt[c*OCpad+oc] = w[oc*C+c] ----------------
__global__ void transposeW_kernel(const float* __restrict__ w, float* __restrict__ wt,
                                  int OC, int OCpad, int C)
{
    int idx = blockIdx.x * blockDim.x + threadIdx.x;
    if (idx >= C * OCpad) return;
    int c = idx / OCpad, oc = idx % OCpad;
    wt[idx] = (oc < OC) ? w[oc * C + c] : 0.f;
}

// scaled variant for branch0 (folds k=1 depthwise weight) + effective bias
__global__ void transposeW_scaled_kernel(const float* __restrict__ w,
                                         const float* __restrict__ scale,
                                         const float* __restrict__ dwb,
                                         const float* __restrict__ pwb,
                                         float* __restrict__ wt,
                                         float* __restrict__ eb,
                                         int OC, int OCpad, int C)
{
    int idx = blockIdx.x * blockDim.x + threadIdx.x;
    if (idx < C * OCpad) {
        int c = idx / OCpad, oc = idx % OCpad;
        wt[idx] = (oc < OC) ? w[oc * C + c] * scale[c] : 0.f;
    }
    if (idx < OC) {
        float s = pwb[idx];
        for (int c = 0; c < C; c++) s += w[idx * C + c] * dwb[c];
        eb[idx] = s;
    }
}

// ---------------- depthwise conv (k = 3,5, SAME padding), 4 px / thread ----------------
template <int KK>
__global__ void dw_conv_kernel(const float* __restrict__ x,
                               const float* __restrict__ w,
                               const float* __restrict__ bias,
                               float* __restrict__ y)
{
    const int P4 = PP / 4;
    int idx = blockIdx.x * blockDim.x + threadIdx.x;
    if (idx >= BN * CF * P4) return;
    int p4 = idx % P4;
    int c  = (idx / P4) % CF;
    int b  = idx / (CF * P4);
    int p  = p4 * 4;
    int h  = p / WW;
    int x0 = p - h * WW;
    const int pad = KK / 2;
    const float* xp = x + ((long)(b * CF + c)) * PP;
    const float* wp = w + c * KK * KK;

    float acc[4];
    float bb = bias[c];
#pragma unroll
    for (int i = 0; i < 4; i++) acc[i] = bb;

    bool inter = (h >= pad) && (h < HH - pad) && (x0 >= pad) && (x0 + 3 + pad < WW);

#pragma unroll
    for (int ky = 0; ky < KK; ky++) {
        int yy = h + ky - pad;
        const float* r = xp + yy * WW + x0 - pad;
        float v[KK + 3];
        if (inter) {
#pragma unroll
            for (int m = 0; m < KK + 3; m++) v[m] = r[m];
        } else {
            bool vy = (yy >= 0) && (yy < HH);
#pragma unroll
            for (int m = 0; m < KK + 3; m++) {
                int xx = x0 - pad + m;
                v[m] = (vy && xx >= 0 && xx < WW) ? xp[yy * WW + xx] : 0.f;
            }
        }
#pragma unroll
        for (int kx = 0; kx < KK; kx++) {
            float wv = wp[ky * KK + kx];
#pragma unroll
            for (int i = 0; i < 4; i++) acc[i] += v[i + kx] * wv;
        }
    }
    float4 o4 = make_float4(acc[0], acc[1], acc[2], acc[3]);
    *reinterpret_cast<float4*>(y + (long)idx * 4) = o4;
}

// ---------------- tf32 pointwise GEMM ----------------
__global__ void pw_gemm_tf32_kernel(const float* __restrict__ X,
                                    const float* __restrict__ Wt,
                                    const float* __restrict__ bias,
                                    float* __restrict__ Y,
                                    int C, int OC, int OCpad,
                                    long xbs, long ybs, long wbs,
                                    int relu, float* __restrict__ msum)
{
    extern __shared__ float smem[];
    float* Xs = smem;                  // [64][XSTR]
    float* Ws = smem + 64 * XSTR;      // [64][WSTR]
    float* red = Ws;                   // mean-mode partials (aliases Ws)

    const int P = PP;
    int b = blockIdx.z;
    const float* Xb = X + (long)b * xbs;
    const float* Wp = Wt + (long)b * wbs;

    int p0 = blockIdx.x * 128;
    int t = threadIdx.x;
    int lane = t & 31, wid = t >> 5;
    int pw = wid * 16;
    int g = lane >> 2, k4 = lane & 3;

    if (C == 64) {
        for (int i = t; i < 2048; i += 256) {
            int cc = i >> 5, q = i & 31;
            float4 v = reinterpret_cast<const float4*>(Xb + (long)cc * P + p0)[q];
            float4 o;
            o.x = __uint_as_float(tf32b(v.x)); o.y = __uint_as_float(tf32b(v.y));
            o.z = __uint_as_float(tf32b(v.z)); o.w = __uint_as_float(tf32b(v.w));
            *reinterpret_cast<float4*>(&Xs[cc * XSTR + q * 4]) = o;
        }
        __syncthreads();

        int nT = OCpad >> 6;
        float* Yb = Y + (long)b * ybs;
        for (int ocT = 0; ocT < nT; ocT++) {
            int oc0 = ocT * 64;
            for (int i = t; i < 4096; i += 256) {
                int cc = i >> 6, oo = i & 63;
                Ws[cc * WSTR + oo] = __uint_as_float(tf32b(Wp[(long)cc * OCpad + oc0 + oo]));
            }
            __syncthreads();

            float acc[8][4];
#pragma unroll
            for (int nt = 0; nt < 8; nt++)
#pragma unroll
                for (int j = 0; j < 4; j++) acc[nt][j] = 0.f;

#pragma unroll
            for (int kc = 0; kc < 8; kc++) {
                int kb = kc * 8 + k4;
                unsigned a0 = __float_as_uint(Xs[kb * XSTR + pw + g]);
                unsigned a1 = __float_as_uint(Xs[kb * XSTR + pw + g + 8]);
                unsigned a2 = __float_as_uint(Xs[(kb + 4) * XSTR + pw + g]);
                unsigned a3 = __float_as_uint(Xs[(kb + 4) * XSTR + pw + g + 8]);
#pragma unroll
                for (int nt = 0; nt < 8; nt++) {
                    unsigned b0 = __float_as_uint(Ws[kb * WSTR + nt * 8 + g]);
                    unsigned b1 = __float_as_uint(Ws[(kb + 4) * WSTR + nt * 8 + g]);
                    mma8(acc[nt], a0, a1, a2, a3, b0, b1);
                }
            }

#pragma unroll
            for (int nt = 0; nt < 8; nt++) {
                int oc = oc0 + nt * 8 + k4 * 2;
                int px = p0 + pw + g;
                if (oc < OC) {
                    float bb = bias[oc];
                    float v0 = acc[nt][0] + bb, v2 = acc[nt][2] + bb;
                    if (relu) { v0 = fmaxf(v0, 0.f); v2 = fmaxf(v2, 0.f); }
                    Yb[(long)oc * P + px]     = v0;
                    Yb[(long)oc * P + px + 8] = v2;
                }
                if (oc + 1 < OC) {
                    float bb = bias[oc + 1];
                    float v1 = acc[nt][1] + bb, v3 = acc[nt][3] + bb;
                    if (relu) { v1 = fmaxf(v1, 0.f); v3 = fmaxf(v3, 0.f); }
                    Yb[(long)(oc + 1) * P + px]     = v1;
                    Yb[(long)(oc + 1) * P + px + 8] = v3;
                }
            }
            __syncthreads();
        }
    } else {
        float acc[8][4];
#pragma unroll
        for (int nt = 0; nt < 8; nt++)
#pragma unroll
            for (int j = 0; j < 4; j++) acc[nt][j] = 0.f;

        for (int c0 = 0; c0 < C; c0 += 64) {
            for (int i = t; i < 2048; i += 256) {
                int cc = i >> 5, q = i & 31;
                float4 v = reinterpret_cast<const float4*>(Xb + (long)(c0 + cc) * P + p0)[q];
                float4 o;
                o.x = __uint_as_float(tf32b(v.x)); o.y = __uint_as_float(tf32b(v.y));
                o.z = __uint_as_float(tf32b(v.z)); o.w = __uint_as_float(tf32b(v.w));
                *reinterpret_cast<float4*>(&Xs[cc * XSTR + q * 4]) = o;
            }
            for (int i = t; i < 4096; i += 256) {
                int cc = i >> 6, oo = i & 63;
                Ws[cc * WSTR + oo] = __uint_as_float(tf32b(Wp[(long)(c0 + cc) * OCpad + oo]));
            }
            __syncthreads();

#pragma unroll
            for (int kc = 0; kc < 8; kc++) {
                int kb = kc * 8 + k4;
                unsigned a0 = __float_as_uint(Xs[kb * XSTR + pw + g]);
                unsigned a1 = __float_as_uint(Xs[kb * XSTR + pw + g + 8]);
                unsigned a2 = __float_as_uint(Xs[(kb + 4) * XSTR + pw + g]);
                unsigned a3 = __float_as_uint(Xs[(kb + 4) * XSTR + pw + g + 8]);
#pragma unroll
                for (int nt = 0; nt < 8; nt++) {
                    unsigned b0 = __float_as_uint(Ws[kb * WSTR + nt * 8 + g]);
                    unsigned b1 = __float_as_uint(Ws[(kb + 4) * WSTR + nt * 8 + g]);
                    mma8(acc[nt], a0, a1, a2, a3, b0, b1);
                }
            }
            __syncthreads();
        }

        if (msum == nullptr) {
            float* Yb = Y + (long)b * ybs;
#pragma unroll
            for (int nt = 0; nt < 8; nt++) {
                int oc = nt * 8 + k4 * 2;
                int px = p0 + pw + g;
                float b0v = bias[oc], b1v = bias[oc + 1];
                float v0 = acc[nt][0] + b0v, v1 = acc[nt][1] + b1v;
                float v2 = acc[nt][2] + b0v, v3 = acc[nt][3] + b1v;
                if (relu) {
                    v0 = fmaxf(v0, 0.f); v1 = fmaxf(v1, 0.f);
                    v2 = fmaxf(v2, 0.f); v3 = fmaxf(v3, 0.f);
                }
                Yb[(long)oc * P + px]           = v0;
                Yb[(long)(oc + 1) * P + px]     = v1;
                Yb[(long)oc * P + px + 8]       = v2;
                Yb[(long)(oc + 1) * P + px + 8] = v3;
            }
        } else {
#pragma unroll
            for (int nt = 0; nt < 8; nt++) {
                int oc = nt * 8 + k4 * 2;
                float b0v = bias[oc], b1v = bias[oc + 1];
                float s0 = fmaxf(acc[nt][0] + b0v, 0.f) + fmaxf(acc[nt][2] + b0v, 0.f);
                float s1 = fmaxf(acc[nt][1] + b1v, 0.f) + fmaxf(acc[nt][3] + b1v, 0.f);
#pragma unroll
                for (int off = 4; off < 32; off <<= 1) {
                    s0 += __shfl_xor_sync(0xffffffff, s0, off);
                    s1 += __shfl_xor_sync(0xffffffff, s1, off);
                }
                if (lane < 4) {
                    red[wid * 64 + oc]     = s0;
                    red[wid * 64 + oc + 1] = s1;
                }
            }
            __syncthreads();
            if (t < 64) {
                float s = 0.f;
#pragma unroll
                for (int w = 0; w < 8; w++) s += red[w * 64 + t];
                msum[((long)b * 64 + t) * gridDim.x + blockIdx.x] = s;
            }
        }
    }
}

// ---------------- finish mean ----------------
__global__ void mean_finish_kernel(const float* __restrict__ msum, float* __restrict__ att)
{
    int o = blockIdx.x, b = blockIdx.y;
    const float* p = msum + ((long)b * 64 + o) * PTILES;
    float s = 0.f;
    for (int i = threadIdx.x; i < PTILES; i += 32) s += p[i];
#pragma unroll
    for (int off = 16; off > 0; off >>= 1) s += __shfl_xor_sync(0xffffffff, s, off);
    if (threadIdx.x == 0) att[b * 64 + o] = s / (float)PP;
}

// ---------------- bilinear sample with border handling ----------------
__device__ __forceinline__ float msample(const float* __restrict__ xc, float py, float px)
{
    float fy0 = floorf(py), fx0 = floorf(px);
    float wy = py - fy0, wx = px - fx0;
    int iy0 = (int)fy0, ix0 = (int)fx0;
    int iy1 = iy0 + 1, ix1 = ix0 + 1;
    bool vy0 = (iy0 >= 0) & (iy0 < HH);
    bool vy1 = (iy1 >= 0) & (iy1 < HH);
    bool vx0 = (ix0 >= 0) & (ix0 < WW);
    bool vx1 = (ix1 >= 0) & (ix1 < WW);
    int cy0 = min(max(iy0, 0), HH - 1);
    int cy1 = min(max(iy1, 0), HH - 1);
    int cx0 = min(max(ix0, 0), WW - 1);
    int cx1 = min(max(ix1, 0), WW - 1);
    float v00 = (vy0 & vx0) ? xc[cy0 * WW + cx0] : 0.f;
    float v01 = (vy0 & vx1) ? xc[cy0 * WW + cx1] : 0.f;
    float v10 = (vy1 & vx0) ? xc[cy1 * WW + cx0] : 0.f;
    float v11 = (vy1 & vx1) ? xc[cy1 * WW + cx1] : 0.f;
    return v00 * (1.f - wy) * (1.f - wx) + v01 * (1.f - wy) * wx +
           v10 * wy * (1.f - wx) + v11 * wy * wx;
}

// ---------------- modulated deformable conv, 2 px / thread, f32x2 accumulate ----------------
template <int KK>
__global__ void mdcn_kernel(const float* __restrict__ xin,
                            const float* __restrict__ om,
                            const float* __restrict__ w,
                            const float* __restrict__ bias,
                            float* __restrict__ out,
                            int branch)
{
    constexpr int K  = KK * KK;
    constexpr int CK = INC * K;
    __shared__ float Ws[CK][64];

    int tid = threadIdx.x;
    for (int i = tid; i < CK * 64; i += blockDim.x) {
        int ck = i >> 6, o = i & 63;
        Ws[ck][o] = w[o * CK + ck];
    }
    __syncthreads();

    int pp = (blockIdx.x * blockDim.x + tid) * 2;   // even pixel pair
    int b = blockIdx.y;
    if (pp >= PP) return;
    int h  = pp / WW;
    int wx = pp - h * WW;                           // wx even; wx+1 same row
    const int pad = KK / 2;

    const float* omb = om + (long)b * (3 * CK) * PP;
    const float* xb  = xin + (long)b * INC * PP;

    u64 acc0[32], acc1[32];
#pragma unroll
    for (int j = 0; j < 32; j++) { acc0[j] = 0ULL; acc1[j] = 0ULL; }

    float by = (float)h - (float)pad;
    float bx = (float)wx - (float)pad;

    for (int c = 0; c < INC; c++) {
        const float* xc = xb + c * PP;
#pragma unroll
        for (int kk = 0; kk < K; kk++) {
            int ck = c * K + kk;
            float2 oy = *reinterpret_cast<const float2*>(omb + (long)(2 * ck) * PP + pp);
            float2 ox = *reinterpret_cast<const float2*>(omb + (long)(2 * ck + 1) * PP + pp);
            float2 mr = *reinterpret_cast<const float2*>(omb + (long)(2 * CK + ck) * PP + pp);
            float m0 = 1.f / (1.f + __expf(-mr.x));
            float m1 = 1.f / (1.f + __expf(-mr.y));

            float ty = (float)(kk / KK) + by;
            float tx = (float)(kk % KK) + bx;

            float s0 = msample(xc, oy.x + ty, ox.x + tx) * m0;
            float s1 = msample(xc, oy.y + ty, ox.y + tx + 1.f) * m1;

            u64 s0p = pack2(s0), s1p = pack2(s1);
            const ulonglong2* wr = reinterpret_cast<const ulonglong2*>(&Ws[ck][0]);
#pragma unroll
            for (int j = 0; j < 16; j++) {
                ulonglong2 w2 = wr[j];
                fma2(acc0[2 * j],     s0p, w2.x);
                fma2(acc0[2 * j + 1], s0p, w2.y);
                fma2(acc1[2 * j],     s1p, w2.x);
                fma2(acc1[2 * j + 1], s1p, w2.y);
            }
        }
    }

    float* ob = out + ((long)(b * 3 + branch) * 64) * PP + pp;
#pragma unroll
    for (int j = 0; j < 32; j++) {
        float2 a0 = unpack2(acc0[j]);   // (ch 2j, ch 2j+1) @ px0
        float2 a1 = unpack2(acc1[j]);   // same channels @ px1
        float b0 = bias[2 * j], b1 = bias[2 * j + 1];
        float2 o0 = make_float2(fmaxf(a0.x + b0, 0.f), fmaxf(a1.x + b0, 0.f));
        float2 o1 = make_float2(fmaxf(a0.y + b1, 0.f), fmaxf(a1.y + b1, 0.f));
        *reinterpret_cast<float2*>(ob + (long)(2 * j) * PP)     = o0;
        *reinterpret_cast<float2*>(ob + (long)(2 * j + 1) * PP) = o1;
    }
}

// ---------------- tiny head ----------------
__global__ void head_kernel(const float* __restrict__ att,
                            const float* __restrict__ fc_w, const float* __restrict__ fc_b,
                            const float* __restrict__ fw0, const float* __restrict__ fb0,
                            const float* __restrict__ fw1, const float* __restrict__ fb1,
                            const float* __restrict__ fw2, const float* __restrict__ fb2,
                            const float* __restrict__ conv_w,
                            float* __restrict__ Wbt, float* __restrict__ atts)
{
    __shared__ float a2[BN][32];
    int t = threadIdx.x;
    if (t < BN * 32) {
        int b = t >> 5, o = t & 31;
        float s = fc_b[o];
        for (int c = 0; c < 64; c++) s += fc_w[o * 64 + c] * att[b * 64 + c];
        a2[b][o] = fmaxf(s, 0.f);
    }
    __syncthreads();
    __shared__ float as[BN][192];
    for (int idx = t; idx < BN * 192; idx += blockDim.x) {
        int b = idx / 192, r = idx % 192;
        int i = r / 64, o = r % 64;
        const float* fw = (i == 0) ? fw0 : ((i == 1) ? fw1 : fw2);
        const float* fb = (i == 0) ? fb0 : ((i == 1) ? fb1 : fb2);
        float s = fb[o];
        for (int c = 0; c < 32; c++) s += fw[o * 32 + c] * a2[b][c];
        as[b][r] = s;
        atts[idx] = s;
    }
    __syncthreads();
    for (int idx = t; idx < BN * 192 * 64; idx += blockDim.x) {
        int b  = idx / (192 * 64);
        int r  = idx % (192 * 64);
        int tc = r / 64;
        int o  = r % 64;
        Wbt[idx] = conv_w[o * 192 + tc] * as[b][tc];
    }
}

// ---------------- launch ----------------
extern "C" void kernel_launch(void* const* d_in, const int* in_sizes, int n_in,
                              void* d_out, int out_size)
{
    (void)in_sizes; (void)n_in; (void)out_size;
    const float* fea    = (const float*)d_in[0];
    const float* inputs = (const float*)d_in[1];
    const float* attn_w = (const float*)d_in[20];
    const float* attn_b = (const float*)d_in[21];
    const float* fc_w   = (const float*)d_in[22];
    const float* fc_b   = (const float*)d_in[23];
    const float* conv_w = (const float*)d_in[30];
    const float* conv_b = (const float*)d_in[31];

    float *dw, *om, *stack, *attp, *att, *atts, *Wt, *Wbt, *eb;
    cudaGetSymbolAddress((void**)&dw, g_dw);
    cudaGetSymbolAddress((void**)&om, g_om);
    cudaGetSymbolAddress((void**)&stack, g_stack);
    cudaGetSymbolAddress((void**)&attp, g_attp);
    cudaGetSymbolAddress((void**)&att, g_att);
    cudaGetSymbolAddress((void**)&atts, g_atts);
    cudaGetSymbolAddress((void**)&Wt, g_Wt);
    cudaGetSymbolAddress((void**)&Wbt, g_Wbt);
    cudaGetSymbolAddress((void**)&eb, g_eb);

    cudaFuncSetAttribute(pw_gemm_tf32_kernel,
                         cudaFuncAttributeMaxDynamicSharedMemorySize, GEMM_SMEM);

    const int wtOff[3]  = {WT_B0, WT_B1, WT_B2};
    const int ocPad[3]  = {64, 192, 576};

    // branch0: fold k=1 dw into transposed weights + effective bias
    transposeW_scaled_kernel<<<(64 * 64 + 255) / 256, 256>>>(
        (const float*)d_in[4], (const float*)d_in[2], (const float*)d_in[3],
        (const float*)d_in[5], Wt + WT_B0, eb, 21, 64, 64);
    for (int i = 1; i < 3; i++) {
        const float* pww = (const float*)d_in[4 + 6 * i];
        int k = 2 * i + 1;
        int oc = INC * 3 * k * k;
        int n = 64 * ocPad[i];
        transposeW_kernel<<<(n + 255) / 256, 256>>>(pww, Wt + wtOff[i], oc, ocPad[i], 64);
    }
    transposeW_kernel<<<(192 * 64 + 255) / 256, 256>>>(attn_w, Wt + WT_ATT, 64, 64, 192);

    for (int i = 0; i < 3; i++) {
        const float* dww  = (const float*)d_in[2 + 6 * i];
        const float* dwb  = (const float*)d_in[3 + 6 * i];
        const float* pwb  = (const float*)d_in[5 + 6 * i];
        const float* dcnw = (const float*)d_in[6 + 6 * i];
        const float* dcnb = (const float*)d_in[7 + 6 * i];
        int k  = 2 * i + 1;
        int oc = INC * 3 * k * k;   // 21, 189, 525

        const float* gx = dw;
        const float* gb = pwb;
        if (i == 0) { gx = fea; gb = eb; }
        else {
            int total4 = BN * CF * PP / 4;
            int blocks = (total4 + 255) / 256;
            if (i == 1) dw_conv_kernel<3><<<blocks, 256>>>(fea, dww, dwb, dw);
            else        dw_conv_kernel<5><<<blocks, 256>>>(fea, dww, dwb, dw);
        }

        dim3 ggrid(PTILES, 1, BN);
        pw_gemm_tf32_kernel<<<ggrid, 256, GEMM_SMEM>>>(gx, Wt + wtOff[i], gb, om,
                                                       64, oc, ocPad[i],
                                                       (long)64 * PP, (long)oc * PP, 0, 0, nullptr);

        dim3 mgrid(PP / 256, BN);
        if (i == 0) mdcn_kernel<1><<<mgrid, 128>>>(inputs, om, dcnw, dcnb, stack, i);
        if (i == 1) mdcn_kernel<3><<<mgrid, 128>>>(inputs, om, dcnw, dcnb, stack, i);
        if (i == 2) mdcn_kernel<5><<<mgrid, 128>>>(inputs, om, dcnw, dcnb, stack, i);
    }

    // attention: relu(pw(stack, attn_w)) -> mean (fused partial sums)
    dim3 agrid(PTILES, 1, BN);
    pw_gemm_tf32_kernel<<<agrid, 256, GEMM_SMEM>>>(stack, Wt + WT_ATT, attn_b, nullptr,
                                                   192, 64, 64,
                                                   (long)192 * PP, 0, 0, 1, attp);
    dim3 rgrid(64, BN);
    mean_finish_kernel<<<rgrid, 32>>>(attp, att);

    head_kernel<<<1, 256>>>(att, fc_w, fc_b,
                            (const float*)d_in[24], (const float*)d_in[25],
                            (const float*)d_in[26], (const float*)d_in[27],
                            (const float*)d_in[28], (const float*)d_in[29],
                            conv_w, Wbt, atts);

    // final: relu(pw(stack, Wbt)) with atts folded into per-batch transposed weights
    pw_gemm_tf32_kernel<<<agrid, 256, GEMM_SMEM>>>(stack, Wbt, conv_b, (float*)d_out,
                                                   192, 64, 64,
                                                   (long)192 * PP, (long)64 * PP, (long)192 * 64, 1, nullptr);
}